// round 3
// baseline (speedup 1.0000x reference)
#include <cuda_runtime.h>
#include <cuda_bf16.h>

#define BATCH 4096
#define NHID  512
#define BR    32
#define NBKT  1024   // bucket key = lab>>5 ; node2 = 33+bkt, node1 = 1+(bkt>>5)

__device__ int d_start[NBKT + 1];
__device__ int d_perm[BATCH];

// ---------------- bucket sort by (lab>>5): single block, 1024 threads ----------------
__global__ __launch_bounds__(1024, 1)
void sort_kernel(const int* __restrict__ labels)
{
    __shared__ int hist[NBKT];
    __shared__ int sa[NBKT];
    __shared__ int sb[NBKT];
    __shared__ int cur[NBKT];
    const int t = threadIdx.x;
    hist[t] = 0;
    __syncthreads();
    int lab[4];
    #pragma unroll
    for (int i = 0; i < 4; i++) {
        lab[i] = labels[t + i * 1024];
        atomicAdd(&hist[lab[i] >> 5], 1);
    }
    __syncthreads();
    sa[t] = hist[t];
    __syncthreads();
    int* src = sa; int* dst = sb;
    for (int o = 1; o < NBKT; o <<= 1) {          // inclusive Hillis-Steele scan
        int v = src[t];
        if (t >= o) v += src[t - o];
        dst[t] = v;
        __syncthreads();
        int* tmp = src; src = dst; dst = tmp;
    }
    const int incl = src[t];
    const int excl = incl - hist[t];
    d_start[t] = excl;
    if (t == 0) d_start[NBKT] = BATCH;
    cur[t] = excl;
    __syncthreads();
    #pragma unroll
    for (int i = 0; i < 4; i++) {
        int p = atomicAdd(&cur[lab[i] >> 5], 1);
        d_perm[p] = t + i * 1024;
    }
}

// ---------------- warp task: S samples x one node ----------------
// lane = output column. Per 4 h: 4 coalesced LDG.32 of W (1 line each, cached),
// S broadcast LDS.128 of staged x, 4*S FMA -> W bytes amortized S-fold in regs.
template<int SMAX, bool FIRST, bool USE_PERM>
__device__ __forceinline__ void hs_task(
    const float* __restrict__ x, const int* __restrict__ labels,
    const float* __restrict__ W, float* __restrict__ out,
    float4* __restrict__ xsv,            // per-warp staging: SMAX*32 float4
    int lane, int node, int shift, int base, int S)
{
    const int idx = base + ((lane < S) ? lane : 0);
    const int sbi = USE_PERM ? d_perm[idx] : idx;
    const int lb  = labels[sbi];
    const int mystep = (lb >> shift) & 31;

    const float* __restrict__ Wn = W + (size_t)node * (NHID * BR) + lane;

    float acc[SMAX];
    #pragma unroll
    for (int s = 0; s < SMAX; s++) acc[s] = 0.f;

    #pragma unroll 1
    for (int c = 0; c < 4; c++) {                    // 4 chunks of 128 h
        __syncwarp();
        #pragma unroll
        for (int s = 0; s < SMAX; s++) {
            const int bs = __shfl_sync(0xffffffffu, sbi, s);
            const float4* xg = reinterpret_cast<const float4*>(x + (size_t)bs * NHID) + c * 32;
            xsv[s * 32 + lane] = xg[lane];
        }
        __syncwarp();
        const float* __restrict__ Wc = Wn + c * 128 * BR;
        #pragma unroll 2
        for (int t = 0; t < 32; t++) {
            const float w0 = __ldg(Wc + (4 * t + 0) * BR);
            const float w1 = __ldg(Wc + (4 * t + 1) * BR);
            const float w2 = __ldg(Wc + (4 * t + 2) * BR);
            const float w3 = __ldg(Wc + (4 * t + 3) * BR);
            #pragma unroll
            for (int s = 0; s < SMAX; s++) {
                const float4 xq = xsv[s * 32 + t];   // broadcast
                acc[s] = fmaf(xq.x, w0, acc[s]);
                acc[s] = fmaf(xq.y, w1, acc[s]);
                acc[s] = fmaf(xq.z, w2, acc[s]);
                acc[s] = fmaf(xq.w, w3, acc[s]);
            }
        }
    }

    // S independent warp softmaxes, ILP-interleaved
    float m[SMAX], e[SMAX], sum[SMAX];
    #pragma unroll
    for (int s = 0; s < SMAX; s++) m[s] = acc[s];
    #pragma unroll
    for (int o = 16; o; o >>= 1) {
        #pragma unroll
        for (int s = 0; s < SMAX; s++)
            m[s] = fmaxf(m[s], __shfl_xor_sync(0xffffffffu, m[s], o));
    }
    #pragma unroll
    for (int s = 0; s < SMAX; s++) { e[s] = __expf(acc[s] - m[s]); sum[s] = e[s]; }
    #pragma unroll
    for (int o = 16; o; o >>= 1) {
        #pragma unroll
        for (int s = 0; s < SMAX; s++)
            sum[s] += __shfl_xor_sync(0xffffffffu, sum[s], o);
    }
    float myp = 0.f;
    #pragma unroll
    for (int s = 0; s < SMAX; s++) {
        const int   st = __shfl_sync(0xffffffffu, mystep, s);
        const float es = __shfl_sync(0xffffffffu, e[s], st);
        if (lane == s) myp = es / sum[s];
    }
    if (lane < S) {
        if (FIRST) out[sbi] = myp;
        else       out[sbi] *= myp;
    }
}

// ---------------- level kernels (4 warps / block, 16KB staging) ----------------
__global__ __launch_bounds__(128, 4)
void level0_kernel(const float* __restrict__ x, const int* __restrict__ labels,
                   const float* __restrict__ W, float* __restrict__ out)
{
    __shared__ float4 stage[4][8 * 32];
    const int warp = threadIdx.x >> 5, lane = threadIdx.x & 31;
    const int task = blockIdx.x * 4 + warp;          // 512 tasks x 8 samples
    hs_task<8, true, false>(x, labels, W, out, stage[warp], lane,
                            /*node=*/0, /*shift=*/10, task * 8, 8);
}

__global__ __launch_bounds__(128, 4)
void level1_kernel(const float* __restrict__ x, const int* __restrict__ labels,
                   const float* __restrict__ W, float* __restrict__ out)
{
    __shared__ float4 stage[4][8 * 32];
    const int warp = threadIdx.x >> 5, lane = threadIdx.x & 31;
    const int g  = blockIdx.x >> 2;                  // 32 level-1 nodes
    const int wg = (blockIdx.x & 3) * 4 + warp;      // 16 warps per node
    const int s0 = d_start[g * 32];
    const int s1 = d_start[(g + 1) * 32];
    const int node = 1 + g;
    for (int base = s0 + wg * 8; base < s1; base += 16 * 8) {
        const int S = min(8, s1 - base);
        hs_task<8, false, true>(x, labels, W, out, stage[warp], lane,
                                node, /*shift=*/5, base, S);
    }
}

__global__ __launch_bounds__(128, 4)
void level2_kernel(const float* __restrict__ x, const int* __restrict__ labels,
                   const float* __restrict__ W, float* __restrict__ out)
{
    __shared__ float4 stage[4][8 * 32];
    const int warp = threadIdx.x >> 5, lane = threadIdx.x & 31;
    const int bkt = blockIdx.x * 4 + warp;           // 1024 buckets
    const int s0 = d_start[bkt], s1 = d_start[bkt + 1];
    const int node = 33 + bkt;
    for (int base = s0; base < s1; base += 4) {
        const int S = min(4, s1 - base);
        hs_task<4, false, true>(x, labels, W, out, stage[warp], lane,
                                node, /*shift=*/0, base, S);
    }
}

extern "C" void kernel_launch(void* const* d_in, const int* in_sizes, int n_in,
                              void* d_out, int out_size)
{
    const float* x      = (const float*)d_in[0];   // [4096, 512] f32
    const int*   labels = (const int*)d_in[1];     // [4096] i32
    const float* W      = (const float*)d_in[2];   // [1057, 512, 32] f32
    float*       out    = (float*)d_out;           // [4096] f32

    sort_kernel  <<<1, 1024>>>(labels);
    level0_kernel<<<128, 128>>>(x, labels, W, out);   // out[b]  = p0
    level1_kernel<<<128, 128>>>(x, labels, W, out);   // out[b] *= p1
    level2_kernel<<<256, 128>>>(x, labels, W, out);   // out[b] *= p2
}

// round 4
// speedup vs baseline: 2.1913x; 2.1913x over previous
#include <cuda_runtime.h>
#include <cuda_bf16.h>

#define BATCH 4096
#define NHID  512
#define BR    32
#define NBKT  1024   // bucket key = lab>>5 ; node2 = 33+bkt, node1 = 1+(bkt>>5)

__device__ int   d_start[NBKT + 1];
__device__ int   d_perm[BATCH];
__device__ float d_p[3][BATCH];     // per-level probabilities

// ---------------- bucket sort by (lab>>5): single block ----------------
__global__ __launch_bounds__(1024, 1)
void sort_kernel(const int* __restrict__ labels)
{
    __shared__ int hist[NBKT];
    __shared__ int sa[NBKT];
    __shared__ int sb[NBKT];
    __shared__ int cur[NBKT];
    const int t = threadIdx.x;
    hist[t] = 0;
    __syncthreads();
    int lab[4];
    #pragma unroll
    for (int i = 0; i < 4; i++) {
        lab[i] = labels[t + i * 1024];
        atomicAdd(&hist[lab[i] >> 5], 1);
    }
    __syncthreads();
    sa[t] = hist[t];
    __syncthreads();
    int* src = sa; int* dst = sb;
    for (int o = 1; o < NBKT; o <<= 1) {          // inclusive Hillis-Steele scan
        int v = src[t];
        if (t >= o) v += src[t - o];
        dst[t] = v;
        __syncthreads();
        int* tmp = src; src = dst; dst = tmp;
    }
    const int incl = src[t];
    const int excl = incl - hist[t];
    d_start[t] = excl;
    if (t == 0) d_start[NBKT] = BATCH;
    cur[t] = excl;
    __syncthreads();
    #pragma unroll
    for (int i = 0; i < 4; i++) {
        int p = atomicAdd(&cur[lab[i] >> 5], 1);
        d_perm[p] = t + i * 1024;
    }
}

// ---------------- group task: SMAX samples x one node, 4-warp h-split ----------------
// Warp q computes partial logits for h in [128q, 128q+128) for all samples:
// 128 coalesced LDG.32 of W (one 128B line each), S register accumulators.
// Partials combined through smem; per-sample warp softmax in the epilogue.
template<int SMAX>
__device__ __forceinline__ void process_group(
    const float* __restrict__ x, const int* __restrict__ labels,
    const float* __restrict__ W, float* __restrict__ pout,
    float4* __restrict__ xsv,        // [SMAX*128] staged x (float4)
    float*  __restrict__ part,       // [4][SMAX][32] partial logits
    int* __restrict__ sid_sm, int* __restrict__ step_sm,
    int node, int shift, int base, int S, bool use_perm)
{
    const int tid  = threadIdx.x;
    const int warp = tid >> 5;
    const int lane = tid & 31;

    if (tid < S) {
        const int sb = use_perm ? d_perm[base + tid] : (base + tid);
        sid_sm[tid]  = sb;
        step_sm[tid] = (labels[sb] >> shift) & 31;
    }
    __syncthreads();

    // Stage x for the S valid samples (128 threads = 128 float4 per sample)
    #pragma unroll
    for (int s = 0; s < SMAX; s++) {
        if (s < S) {
            const float4* xg = reinterpret_cast<const float4*>(x + (size_t)sid_sm[s] * NHID);
            xsv[s * 128 + tid] = xg[tid];
        }
    }
    __syncthreads();

    const float* __restrict__ Wq =
        W + (size_t)node * (NHID * BR) + (warp * 128) * BR + lane;

    float acc[SMAX];
    #pragma unroll
    for (int s = 0; s < SMAX; s++) acc[s] = 0.f;

    #pragma unroll 4
    for (int t = 0; t < 32; t++) {
        const float w0 = __ldg(Wq + (4 * t + 0) * BR);
        const float w1 = __ldg(Wq + (4 * t + 1) * BR);
        const float w2 = __ldg(Wq + (4 * t + 2) * BR);
        const float w3 = __ldg(Wq + (4 * t + 3) * BR);
        #pragma unroll
        for (int s = 0; s < SMAX; s++) {
            const float4 xq = xsv[s * 128 + warp * 32 + t];   // broadcast LDS.128
            acc[s] = fmaf(xq.x, w0, acc[s]);
            acc[s] = fmaf(xq.y, w1, acc[s]);
            acc[s] = fmaf(xq.z, w2, acc[s]);
            acc[s] = fmaf(xq.w, w3, acc[s]);
        }
    }

    #pragma unroll
    for (int s = 0; s < SMAX; s++)
        part[(warp * SMAX + s) * 32 + lane] = acc[s];
    __syncthreads();

    // Epilogue: warp w finishes samples si = w, w+4, ...
    #pragma unroll
    for (int si = warp; si < SMAX; si += 4) {
        float logit = part[(0 * SMAX + si) * 32 + lane]
                    + part[(1 * SMAX + si) * 32 + lane]
                    + part[(2 * SMAX + si) * 32 + lane]
                    + part[(3 * SMAX + si) * 32 + lane];
        float m = logit;
        #pragma unroll
        for (int o = 16; o; o >>= 1) m = fmaxf(m, __shfl_xor_sync(0xffffffffu, m, o));
        const float e = __expf(logit - m);
        float ssum = e;
        #pragma unroll
        for (int o = 16; o; o >>= 1) ssum += __shfl_xor_sync(0xffffffffu, ssum, o);
        if (si < S) {
            const float es = __shfl_sync(0xffffffffu, e, step_sm[si]);
            if (lane == 0) pout[sid_sm[si]] = es / ssum;
        }
    }
    __syncthreads();   // protect smem reuse across loop iterations
}

// ---------------- unified levels kernel ----------------
// blocks [0,512):    level 0, S=8, consecutive samples (no perm)
// blocks [512,768):  level 1, 32 nodes x 8 group-slots, S=8, perm
// blocks [768,1792): level 2, one bucket each, S=4, perm, loop over groups
__global__ __launch_bounds__(128)
void levels_kernel(const float* __restrict__ x,
                   const int* __restrict__ labels,
                   const float* __restrict__ W)
{
    __shared__ float4 xsv[8 * 128];        // 16 KB
    __shared__ float  part[4 * 8 * 32];    // 4 KB
    __shared__ int    sid_sm[8];
    __shared__ int    step_sm[8];

    const int blk = blockIdx.x;

    if (blk < 512) {
        process_group<8>(x, labels, W, d_p[0], xsv, part, sid_sm, step_sm,
                         /*node=*/0, /*shift=*/10, blk * 8, 8, false);
    } else if (blk < 768) {
        const int z = blk - 512;
        const int g = z >> 3;
        const int j = z & 7;
        const int s0 = d_start[g * 32];
        const int s1 = d_start[g * 32 + 32];
        const int node = 1 + g;
        for (int base = s0 + j * 8; base < s1; base += 64) {
            const int S = min(8, s1 - base);
            process_group<8>(x, labels, W, d_p[1], xsv, part, sid_sm, step_sm,
                             node, /*shift=*/5, base, S, true);
        }
    } else {
        const int bkt = blk - 768;
        const int s0 = d_start[bkt];
        const int s1 = d_start[bkt + 1];
        const int node = 33 + bkt;
        for (int base = s0; base < s1; base += 4) {
            const int S = min(4, s1 - base);
            process_group<4>(x, labels, W, d_p[2], xsv, part, sid_sm, step_sm,
                             node, /*shift=*/0, base, S, true);
        }
    }
}

__global__ __launch_bounds__(256)
void combine_kernel(float* __restrict__ out)
{
    const int b = blockIdx.x * 256 + threadIdx.x;
    out[b] = d_p[0][b] * d_p[1][b] * d_p[2][b];
}

extern "C" void kernel_launch(void* const* d_in, const int* in_sizes, int n_in,
                              void* d_out, int out_size)
{
    const float* x      = (const float*)d_in[0];   // [4096, 512] f32
    const int*   labels = (const int*)d_in[1];     // [4096] i32
    const float* W      = (const float*)d_in[2];   // [1057, 512, 32] f32
    float*       out    = (float*)d_out;           // [4096] f32

    sort_kernel   <<<1, 1024>>>(labels);
    levels_kernel <<<1792, 128>>>(x, labels, W);
    combine_kernel<<<BATCH / 256, 256>>>(out);
}

// round 5
// speedup vs baseline: 2.8219x; 1.2878x over previous
#include <cuda_runtime.h>
#include <cuda_bf16.h>

#define BATCH 4096
#define NHID  512
#define BR    32
#define NBKT  1024   // bucket key = lab>>5 ; node2 = 33+bkt, node1 = 1+(bkt>>5)

#define L0_BLOCKS 512          // 4096/8 groups, S=8
#define L1_SLOTS  544          // >= 32 + 4096/8 worst-case level-1 groups (S=8)
#define L2_SLOTS  2048         // >= 1024 + 4096/4 worst-case level-2 groups (S=4)

__device__ int   d_start[NBKT + 1];
__device__ int   d_perm[BATCH];
__device__ int   d_g1off[33];        // prefix of level-1 group counts per node
__device__ int   d_g2off[NBKT + 1];  // prefix of level-2 group counts per bucket
__device__ float d_p[3][BATCH];      // per-level probabilities

// ---------------- sort + task-table kernel: single block, warp-scan based ----------------
__global__ __launch_bounds__(1024, 1)
void sort_kernel(const int* __restrict__ labels)
{
    __shared__ int hist[NBKT];
    __shared__ int wsum[32];
    __shared__ int cur[NBKT];
    __shared__ int l1cnt[32];

    const int t    = threadIdx.x;
    const int wid  = t >> 5;
    const int lane = t & 31;

    hist[t] = 0;
    __syncthreads();
    int lab[4];
    #pragma unroll
    for (int i = 0; i < 4; i++) {
        lab[i] = labels[t + i * 1024];
        atomicAdd(&hist[lab[i] >> 5], 1);
    }
    __syncthreads();

    // ---- exclusive scan of hist via warp scans ----
    const int h = hist[t];
    int v = h;
    #pragma unroll
    for (int o = 1; o < 32; o <<= 1) {
        int u = __shfl_up_sync(0xffffffffu, v, o);
        if (lane >= o) v += u;
    }
    if (lane == 31) wsum[wid] = v;
    __syncthreads();
    if (wid == 0) {
        int w = wsum[lane];
        #pragma unroll
        for (int o = 1; o < 32; o <<= 1) {
            int u = __shfl_up_sync(0xffffffffu, w, o);
            if (lane >= o) w += u;
        }
        wsum[lane] = w;
    }
    __syncthreads();
    const int incl = v + (wid > 0 ? wsum[wid - 1] : 0);
    const int excl = incl - h;
    d_start[t] = excl;
    if (t == 0) d_start[NBKT] = BATCH;
    cur[t] = excl;
    __syncthreads();

    // ---- scatter ----
    #pragma unroll
    for (int i = 0; i < 4; i++) {
        int p = atomicAdd(&cur[lab[i] >> 5], 1);
        d_perm[p] = t + i * 1024;
    }

    // ---- level-2 group prefix: g2 = ceil(n_bkt / 4) ----
    int g2 = (h + 3) >> 2;
    int v2 = g2;
    #pragma unroll
    for (int o = 1; o < 32; o <<= 1) {
        int u = __shfl_up_sync(0xffffffffu, v2, o);
        if (lane >= o) v2 += u;
    }
    __syncthreads();            // wsum reuse
    if (lane == 31) wsum[wid] = v2;
    __syncthreads();
    if (wid == 0) {
        int w = wsum[lane];
        #pragma unroll
        for (int o = 1; o < 32; o <<= 1) {
            int u = __shfl_up_sync(0xffffffffu, w, o);
            if (lane >= o) w += u;
        }
        wsum[lane] = w;
    }
    __syncthreads();
    const int incl2 = v2 + (wid > 0 ? wsum[wid - 1] : 0);
    d_g2off[t] = incl2 - g2;
    if (t == 1023) d_g2off[NBKT] = incl2;

    // ---- level-1 group prefix: node w has buckets [32w, 32w+32) ----
    {
        int c = hist[wid * 32 + lane];
        #pragma unroll
        for (int o = 16; o; o >>= 1) c += __shfl_xor_sync(0xffffffffu, c, o);
        if (lane == 0) l1cnt[wid] = (c + 7) >> 3;   // ceil(n_node/8)
    }
    __syncthreads();
    if (t == 0) {
        int acc = 0;
        d_g1off[0] = 0;
        #pragma unroll
        for (int g = 0; g < 32; g++) { acc += l1cnt[g]; d_g1off[g + 1] = acc; }
    }
}

// largest k with off[k] <= i  (off has n+1 entries, off[0]=0)
__device__ __forceinline__ int find_bucket(const int* __restrict__ off, int n, int i)
{
    int lo = 0, hi = n;
    while (lo + 1 < hi) {
        int mid = (lo + hi) >> 1;
        if (off[mid] <= i) lo = mid; else hi = mid;
    }
    return lo;
}

// ---------------- group task: SMAX samples x one node, 4-warp h-split ----------------
template<int SMAX>
__device__ __forceinline__ void process_group(
    const float* __restrict__ x, const int* __restrict__ labels,
    const float* __restrict__ W, float* __restrict__ pout,
    float4* __restrict__ xsv,        // [SMAX*128]
    float*  __restrict__ part,       // [4][SMAX][32]
    int* __restrict__ sid_sm, int* __restrict__ step_sm,
    int node, int shift, int base, int S, bool use_perm)
{
    const int tid  = threadIdx.x;
    const int warp = tid >> 5;
    const int lane = tid & 31;

    if (tid < S) {
        const int sb = use_perm ? d_perm[base + tid] : (base + tid);
        sid_sm[tid]  = sb;
        step_sm[tid] = (labels[sb] >> shift) & 31;
    }
    __syncthreads();

    #pragma unroll
    for (int s = 0; s < SMAX; s++) {
        if (s < S) {
            const float4* xg = reinterpret_cast<const float4*>(x + (size_t)sid_sm[s] * NHID);
            xsv[s * 128 + tid] = xg[tid];
        }
    }
    __syncthreads();

    const float* __restrict__ Wq =
        W + (size_t)node * (NHID * BR) + (warp * 128) * BR + lane;

    float acc[SMAX];
    #pragma unroll
    for (int s = 0; s < SMAX; s++) acc[s] = 0.f;

    #pragma unroll 4
    for (int t = 0; t < 32; t++) {
        const float w0 = __ldg(Wq + (4 * t + 0) * BR);
        const float w1 = __ldg(Wq + (4 * t + 1) * BR);
        const float w2 = __ldg(Wq + (4 * t + 2) * BR);
        const float w3 = __ldg(Wq + (4 * t + 3) * BR);
        #pragma unroll
        for (int s = 0; s < SMAX; s++) {
            const float4 xq = xsv[s * 128 + warp * 32 + t];   // broadcast LDS.128
            acc[s] = fmaf(xq.x, w0, acc[s]);
            acc[s] = fmaf(xq.y, w1, acc[s]);
            acc[s] = fmaf(xq.z, w2, acc[s]);
            acc[s] = fmaf(xq.w, w3, acc[s]);
        }
    }

    #pragma unroll
    for (int s = 0; s < SMAX; s++)
        part[(warp * SMAX + s) * 32 + lane] = acc[s];
    __syncthreads();

    #pragma unroll
    for (int si = warp; si < SMAX; si += 4) {
        float logit = part[(0 * SMAX + si) * 32 + lane]
                    + part[(1 * SMAX + si) * 32 + lane]
                    + part[(2 * SMAX + si) * 32 + lane]
                    + part[(3 * SMAX + si) * 32 + lane];
        float m = logit;
        #pragma unroll
        for (int o = 16; o; o >>= 1) m = fmaxf(m, __shfl_xor_sync(0xffffffffu, m, o));
        const float e = __expf(logit - m);
        float ssum = e;
        #pragma unroll
        for (int o = 16; o; o >>= 1) ssum += __shfl_xor_sync(0xffffffffu, ssum, o);
        if (si < S) {
            const float es = __shfl_sync(0xffffffffu, e, step_sm[si]);
            if (lane == 0) pout[sid_sm[si]] = es / ssum;
        }
    }
}

// ---------------- unified levels kernel: exactly ONE group per block ----------------
__global__ __launch_bounds__(128)
void levels_kernel(const float* __restrict__ x,
                   const int* __restrict__ labels,
                   const float* __restrict__ W)
{
    __shared__ float4 xsv[8 * 128];        // 16 KB
    __shared__ float  part[4 * 8 * 32];    // 4 KB
    __shared__ int    sid_sm[8];
    __shared__ int    step_sm[8];

    const int blk = blockIdx.x;

    if (blk < L0_BLOCKS) {
        process_group<8>(x, labels, W, d_p[0], xsv, part, sid_sm, step_sm,
                         /*node=*/0, /*shift=*/10, blk * 8, 8, false);
    } else if (blk < L0_BLOCKS + L1_SLOTS) {
        const int i = blk - L0_BLOCKS;
        if (i >= d_g1off[32]) return;
        const int g    = find_bucket(d_g1off, 32, i);
        const int base = d_start[g * 32] + (i - d_g1off[g]) * 8;
        const int S    = min(8, d_start[g * 32 + 32] - base);
        process_group<8>(x, labels, W, d_p[1], xsv, part, sid_sm, step_sm,
                         1 + g, /*shift=*/5, base, S, true);
    } else {
        const int i = blk - (L0_BLOCKS + L1_SLOTS);
        if (i >= d_g2off[NBKT]) return;
        const int k    = find_bucket(d_g2off, NBKT, i);
        const int base = d_start[k] + (i - d_g2off[k]) * 4;
        const int S    = min(4, d_start[k + 1] - base);
        process_group<4>(x, labels, W, d_p[2], xsv, part, sid_sm, step_sm,
                         33 + k, /*shift=*/0, base, S, true);
    }
}

__global__ __launch_bounds__(256)
void combine_kernel(float* __restrict__ out)
{
    const int b = blockIdx.x * 256 + threadIdx.x;
    out[b] = d_p[0][b] * d_p[1][b] * d_p[2][b];
}

extern "C" void kernel_launch(void* const* d_in, const int* in_sizes, int n_in,
                              void* d_out, int out_size)
{
    const float* x      = (const float*)d_in[0];   // [4096, 512] f32
    const int*   labels = (const int*)d_in[1];     // [4096] i32
    const float* W      = (const float*)d_in[2];   // [1057, 512, 32] f32
    float*       out    = (float*)d_out;           // [4096] f32

    sort_kernel   <<<1, 1024>>>(labels);
    levels_kernel <<<L0_BLOCKS + L1_SLOTS + L2_SLOTS, 128>>>(x, labels, W);
    combine_kernel<<<BATCH / 256, 256>>>(out);
}